// round 7
// baseline (speedup 1.0000x reference)
#include <cuda_runtime.h>

// Problem constants
#define B_    2
#define L_    2048
#define DM    768
#define H_    12
#define FEAT  16
#define HD    64
#define BH    (B_ * H_)      // 24
#define MTOT  (B_ * L_)      // 4096

// Scratch (device globals; no allocation allowed)
__device__ float g_q[B_ * H_ * L_ * FEAT];   // [b,h,l,16]
__device__ float g_k[B_ * H_ * L_ * FEAT];   // [b,h,l,16]
__device__ float g_v[B_ * H_ * L_ * HD];     // [b,h,l,64]
__device__ float g_y[B_ * L_ * DM];          // [b,l,h*64]

// ---------------------------------------------------------------------------
// Tiled SGEMM: C = X * W^T, X [MTOT, DM] row-major, W [NCOLS, DM] row-major.
// Output remapped to [b, h, l, HDIM] layout (HOUT=1,HDIM=DM => plain row-major).
// Tile 64x64, k-tile 16, 256 threads, 4x4 microtile.
// ---------------------------------------------------------------------------
template <int NCOLS, int HOUT, int HDIM>
__global__ __launch_bounds__(256)
void sgemm_proj(const float* __restrict__ X, const float* __restrict__ W,
                float* __restrict__ dst) {
    __shared__ float Xs[16][68];
    __shared__ float Ws[16][68];

    const int tid = threadIdx.x;
    const int ty = tid >> 4;          // 0..15
    const int tx = tid & 15;          // 0..15
    const int row0 = blockIdx.y * 64;
    const int col0 = blockIdx.x * 64;

    const int lrow = tid >> 2;        // 0..63
    const int lkq  = (tid & 3) * 4;   // 0,4,8,12

    const float* Xp = X + (row0 + lrow) * DM + lkq;
    const float* Wp = W + (col0 + lrow) * DM + lkq;

    float acc[4][4];
    #pragma unroll
    for (int i = 0; i < 4; i++)
        #pragma unroll
        for (int j = 0; j < 4; j++) acc[i][j] = 0.0f;

    for (int kt = 0; kt < DM; kt += 16) {
        const float4 xv = *(const float4*)(Xp + kt);
        const float4 wv = *(const float4*)(Wp + kt);
        __syncthreads();
        Xs[lkq + 0][lrow] = xv.x; Xs[lkq + 1][lrow] = xv.y;
        Xs[lkq + 2][lrow] = xv.z; Xs[lkq + 3][lrow] = xv.w;
        Ws[lkq + 0][lrow] = wv.x; Ws[lkq + 1][lrow] = wv.y;
        Ws[lkq + 2][lrow] = wv.z; Ws[lkq + 3][lrow] = wv.w;
        __syncthreads();
        #pragma unroll
        for (int k = 0; k < 16; k++) {
            const float4 a4 = *(const float4*)&Xs[k][ty * 4];
            const float4 b4 = *(const float4*)&Ws[k][tx * 4];
            const float av[4] = {a4.x, a4.y, a4.z, a4.w};
            const float bv[4] = {b4.x, b4.y, b4.z, b4.w};
            #pragma unroll
            for (int i = 0; i < 4; i++)
                #pragma unroll
                for (int j = 0; j < 4; j++)
                    acc[i][j] = fmaf(av[i], bv[j], acc[i][j]);
        }
    }

    #pragma unroll
    for (int i = 0; i < 4; i++) {
        const int r  = row0 + ty * 4 + i;
        const int bb = r >> 11;            // / L_
        const int l  = r & (L_ - 1);
        #pragma unroll
        for (int j = 0; j < 4; j++) {
            const int c = col0 + tx * 4 + j;
            const int h = c / HDIM;
            const int e = c % HDIM;
            dst[((bb * HOUT + h) * L_ + l) * HDIM + e] = acc[i][j];
        }
    }
}

// ---------------------------------------------------------------------------
// Attention: for each (b,h), q-tile of 64 rows, loop over all 32 key tiles.
//   s = q.k (16-dim),  A = 1 + s/4 + s^2/32,  weight 2 if m<=n else 1.
//   y_n = (sum_m A_w v_m) / (sum_m A_w)
// ---------------------------------------------------------------------------
__global__ __launch_bounds__(256)
void attn_kernel() {
    __shared__ float Qts[16][68];
    __shared__ float Kts[16][68];
    __shared__ float Vs[64][64];
    __shared__ float As[64][68];
    __shared__ float rowsum[64];

    const int tid = threadIdx.x;
    const int ty = tid >> 4;          // 0..15
    const int tx = tid & 15;          // 0..15
    const int qt = blockIdx.x;        // 0..31
    const int bh = blockIdx.y;        // 0..23

    const float* qbase = g_q + (size_t)bh * L_ * FEAT;
    const float* kbase = g_k + (size_t)bh * L_ * FEAT;
    const float* vbase = g_v + (size_t)bh * L_ * HD;

    const int lrow = tid >> 2;        // 0..63
    const int lfq  = (tid & 3) * 4;   // 0,4,8,12

    // Load Q tile, transposed (feature-major) into smem
    {
        const float4 qv = *(const float4*)(qbase + (qt * 64 + lrow) * FEAT + lfq);
        Qts[lfq + 0][lrow] = qv.x; Qts[lfq + 1][lrow] = qv.y;
        Qts[lfq + 2][lrow] = qv.z; Qts[lfq + 3][lrow] = qv.w;
    }

    float acc[4][4];
    float rsum[4] = {0.0f, 0.0f, 0.0f, 0.0f};
    #pragma unroll
    for (int i = 0; i < 4; i++)
        #pragma unroll
        for (int j = 0; j < 4; j++) acc[i][j] = 0.0f;

    const int n_g0 = qt * 64 + ty * 4;   // query rows n_g0 + i

    for (int ktile = 0; ktile < 32; ktile++) {
        __syncthreads();   // previous AV done reading Vs/As (and Kts)

        // Load K tile transposed
        {
            const float4 kv = *(const float4*)(kbase + (ktile * 64 + lrow) * FEAT + lfq);
            Kts[lfq + 0][lrow] = kv.x; Kts[lfq + 1][lrow] = kv.y;
            Kts[lfq + 2][lrow] = kv.z; Kts[lfq + 3][lrow] = kv.w;
        }
        // Load V tile (row-major [m][e])
        #pragma unroll
        for (int r = 0; r < 4; r++) {
            const int idx = tid + r * 256;          // float4 index, 0..1023
            const int row = idx >> 4;
            const int c4  = (idx & 15) * 4;
            *(float4*)&Vs[row][c4] =
                *(const float4*)(vbase + (ktile * 64 + row) * HD + c4);
        }
        __syncthreads();

        // S = Q K^T for this thread's 4x4 block
        float s[4][4];
        #pragma unroll
        for (int i = 0; i < 4; i++)
            #pragma unroll
            for (int j = 0; j < 4; j++) s[i][j] = 0.0f;

        #pragma unroll
        for (int k = 0; k < 16; k++) {
            const float4 q4 = *(const float4*)&Qts[k][ty * 4];
            const float4 k4 = *(const float4*)&Kts[k][tx * 4];
            const float qa[4] = {q4.x, q4.y, q4.z, q4.w};
            const float ka[4] = {k4.x, k4.y, k4.z, k4.w};
            #pragma unroll
            for (int i = 0; i < 4; i++)
                #pragma unroll
                for (int j = 0; j < 4; j++)
                    s[i][j] = fmaf(qa[i], ka[j], s[i][j]);
        }

        // A = f(s) * weight, store to As[n][m], accumulate row sums
        const int m_g0 = ktile * 64 + tx * 4;
        #pragma unroll
        for (int i = 0; i < 4; i++) {
            float aw[4];
            #pragma unroll
            for (int j = 0; j < 4; j++) {
                const float sv = s[i][j];
                float a = fmaf(sv, fmaf(sv, 0.03125f, 0.25f), 1.0f);
                if (m_g0 + j <= n_g0 + i) a += a;   // causal double-count
                aw[j] = a;
                rsum[i] += a;
            }
            *(float4*)&As[ty * 4 + i][tx * 4] =
                make_float4(aw[0], aw[1], aw[2], aw[3]);
        }
        __syncthreads();

        // acc += A * V   (m unrolled by 4, all smem reads are float4)
        #pragma unroll 4
        for (int m = 0; m < 64; m += 4) {
            const float4 v0 = *(const float4*)&Vs[m + 0][tx * 4];
            const float4 v1 = *(const float4*)&Vs[m + 1][tx * 4];
            const float4 v2 = *(const float4*)&Vs[m + 2][tx * 4];
            const float4 v3 = *(const float4*)&Vs[m + 3][tx * 4];
            const float vv[4][4] = {
                {v0.x, v0.y, v0.z, v0.w},
                {v1.x, v1.y, v1.z, v1.w},
                {v2.x, v2.y, v2.z, v2.w},
                {v3.x, v3.y, v3.z, v3.w},
            };
            #pragma unroll
            for (int i = 0; i < 4; i++) {
                const float4 a4 = *(const float4*)&As[ty * 4 + i][m];
                const float ag[4] = {a4.x, a4.y, a4.z, a4.w};
                #pragma unroll
                for (int g = 0; g < 4; g++)
                    #pragma unroll
                    for (int j = 0; j < 4; j++)
                        acc[i][j] = fmaf(ag[g], vv[g][j], acc[i][j]);
            }
        }
    }

    // Reduce row sums across the 16 tx lanes (within half-warp)
    #pragma unroll
    for (int i = 0; i < 4; i++) {
        float r = rsum[i];
        r += __shfl_xor_sync(0xffffffffu, r, 1);
        r += __shfl_xor_sync(0xffffffffu, r, 2);
        r += __shfl_xor_sync(0xffffffffu, r, 4);
        r += __shfl_xor_sync(0xffffffffu, r, 8);
        if (tx == 0) rowsum[ty * 4 + i] = r;
    }
    __syncthreads();

    // Epilogue: scale by z = 1/rowsum, write y in [b, l, h*64] layout
    const int bb = bh / H_;
    const int h  = bh % H_;
    #pragma unroll
    for (int i = 0; i < 4; i++) {
        const float z = 1.0f / rowsum[ty * 4 + i];
        const int n_g = qt * 64 + ty * 4 + i;
        const float4 o = make_float4(acc[i][0] * z, acc[i][1] * z,
                                     acc[i][2] * z, acc[i][3] * z);
        *(float4*)&g_y[((size_t)(bb * L_ + n_g)) * DM + h * HD + tx * 4] = o;
    }
}

// ---------------------------------------------------------------------------
extern "C" void kernel_launch(void* const* d_in, const int* in_sizes, int n_in,
                              void* d_out, int out_size) {
    (void)in_sizes; (void)n_in; (void)out_size;
    const float* hs = (const float*)d_in[0];
    const float* Wq = (const float*)d_in[1];
    const float* Wk = (const float*)d_in[2];
    const float* Wv = (const float*)d_in[3];
    const float* Wo = (const float*)d_in[4];
    float* out = (float*)d_out;

    float *qp, *kp, *vp, *yp;
    cudaGetSymbolAddress((void**)&qp, g_q);
    cudaGetSymbolAddress((void**)&kp, g_k);
    cudaGetSymbolAddress((void**)&vp, g_v);
    cudaGetSymbolAddress((void**)&yp, g_y);

    // Q, K projections: [4096,768] x [192,768]^T -> [b,h,l,16]
    sgemm_proj<192, H_, FEAT><<<dim3(3, MTOT / 64), 256>>>(hs, Wq, qp);
    sgemm_proj<192, H_, FEAT><<<dim3(3, MTOT / 64), 256>>>(hs, Wk, kp);
    // V projection: [4096,768] x [768,768]^T -> [b,h,l,64]
    sgemm_proj<768, H_, HD><<<dim3(12, MTOT / 64), 256>>>(hs, Wv, vp);
    // Attention
    attn_kernel<<<dim3(L_ / 64, BH), 256>>>();
    // Output projection: y [4096,768] x Wo[768,768]^T -> out (row-major)
    sgemm_proj<768, 1, DM><<<dim3(12, MTOT / 64), 256>>>(yp, Wo, out);
}

// round 11
// speedup vs baseline: 1.5402x; 1.5402x over previous
#include <cuda_runtime.h>

// Problem constants
#define B_    2
#define L_    2048
#define DM    768
#define H_    12
#define FEAT  16
#define HD    64
#define BH    (B_ * H_)      // 24
#define MTOT  (B_ * L_)      // 4096
#define NF    153            // 1 + 16 + 136 symmetric degree-2 features
#define NCH   32             // chunks of 64 keys
#define NSE   (NF * HD)      // 9792

// Scratch (device globals; no allocation allowed)
__device__ float g_q[BH * L_ * FEAT];     // [b,h,l,16]
__device__ float g_k[BH * L_ * FEAT];     // [b,h,l,16]
__device__ float g_v[BH * L_ * HD];       // [b,h,l,64]
__device__ float g_y[MTOT * DM];          // [b,l,h*64]
__device__ float g_P[BH * NCH * NF * HD]; // per-chunk state sums
__device__ float g_C[BH * NCH * NF * HD]; // combined prefix+total states
__device__ float g_Pd[BH * NCH * NF];     // per-chunk denominator sums
__device__ float g_Cd[BH * NCH * NF];     // combined denominator

// ---------------------------------------------------------------------------
// Tiled SGEMM: C = X * W^T  (unchanged from previous round)
// ---------------------------------------------------------------------------
template <int NCOLS, int HOUT, int HDIM>
__global__ __launch_bounds__(256)
void sgemm_proj(const float* __restrict__ X, const float* __restrict__ W,
                float* __restrict__ dst) {
    __shared__ __align__(16) float Xs[16][68];
    __shared__ __align__(16) float Ws[16][68];

    const int tid = threadIdx.x;
    const int ty = tid >> 4;
    const int tx = tid & 15;
    const int row0 = blockIdx.y * 64;
    const int col0 = blockIdx.x * 64;

    const int lrow = tid >> 2;
    const int lkq  = (tid & 3) * 4;

    const float* Xp = X + (row0 + lrow) * DM + lkq;
    const float* Wp = W + (col0 + lrow) * DM + lkq;

    float acc[4][4];
    #pragma unroll
    for (int i = 0; i < 4; i++)
        #pragma unroll
        for (int j = 0; j < 4; j++) acc[i][j] = 0.0f;

    for (int kt = 0; kt < DM; kt += 16) {
        const float4 xv = *(const float4*)(Xp + kt);
        const float4 wv = *(const float4*)(Wp + kt);
        __syncthreads();
        Xs[lkq + 0][lrow] = xv.x; Xs[lkq + 1][lrow] = xv.y;
        Xs[lkq + 2][lrow] = xv.z; Xs[lkq + 3][lrow] = xv.w;
        Ws[lkq + 0][lrow] = wv.x; Ws[lkq + 1][lrow] = wv.y;
        Ws[lkq + 2][lrow] = wv.z; Ws[lkq + 3][lrow] = wv.w;
        __syncthreads();
        #pragma unroll
        for (int k = 0; k < 16; k++) {
            const float4 a4 = *(const float4*)&Xs[k][ty * 4];
            const float4 b4 = *(const float4*)&Ws[k][tx * 4];
            const float av[4] = {a4.x, a4.y, a4.z, a4.w};
            const float bv[4] = {b4.x, b4.y, b4.z, b4.w};
            #pragma unroll
            for (int i = 0; i < 4; i++)
                #pragma unroll
                for (int j = 0; j < 4; j++)
                    acc[i][j] = fmaf(av[i], bv[j], acc[i][j]);
        }
    }

    #pragma unroll
    for (int i = 0; i < 4; i++) {
        const int r  = row0 + ty * 4 + i;
        const int bb = r >> 11;
        const int l  = r & (L_ - 1);
        #pragma unroll
        for (int j = 0; j < 4; j++) {
            const int c = col0 + tx * 4 + j;
            const int h = c / HDIM;
            const int e = c % HDIM;
            dst[((bb * HOUT + h) * L_ + l) * HDIM + e] = acc[i][j];
        }
    }
}

// ---------------------------------------------------------------------------
// Build per-chunk state: P[bh][t][f][e], chunk = 64 keys.
// f=0: sum v ; f=1+a: (1/4) sum k_a v ; f=17+idx(a,b), a<=b:
//   diag: (1/32) sum k_a^2 v ; offdiag: (2/32) sum k_a k_b v
// ---------------------------------------------------------------------------
__global__ __launch_bounds__(256)
void build_state() {
    __shared__ __align__(16) float Ks[64][16];
    __shared__ __align__(16) float Vs[64][64];

    const int tid = threadIdx.x;
    const int ty = tid >> 4;          // a index (0..15)
    const int tx = tid & 15;          // e-group
    const int t  = blockIdx.x;
    const int bh = blockIdx.y;

    const float* kbase = g_k + ((size_t)bh * L_ + t * 64) * FEAT;
    const float* vbase = g_v + ((size_t)bh * L_ + t * 64) * HD;

    {
        const int row = tid >> 2, c = (tid & 3) * 4;
        *(float4*)&Ks[row][c] = *(const float4*)(kbase + row * FEAT + c);
    }
    #pragma unroll
    for (int r = 0; r < 4; r++) {
        const int idx = tid + r * 256;
        const int row = idx >> 4, c = (idx & 15) * 4;
        *(float4*)&Vs[row][c] = *(const float4*)(vbase + row * HD + c);
    }
    __syncthreads();

    float acc2[16][4];
    float acc1[4] = {0, 0, 0, 0};
    float acc0[4] = {0, 0, 0, 0};
    #pragma unroll
    for (int b = 0; b < 16; b++)
        #pragma unroll
        for (int j = 0; j < 4; j++) acc2[b][j] = 0.0f;

    const int tyw = ty & 14;   // warp-uniform lower bound for b-loop

    for (int m = 0; m < 64; m++) {
        const float4 k0 = *(const float4*)&Ks[m][0];
        const float4 k1 = *(const float4*)&Ks[m][4];
        const float4 k2 = *(const float4*)&Ks[m][8];
        const float4 k3 = *(const float4*)&Ks[m][12];
        const float kb[16] = {k0.x, k0.y, k0.z, k0.w, k1.x, k1.y, k1.z, k1.w,
                              k2.x, k2.y, k2.z, k2.w, k3.x, k3.y, k3.z, k3.w};
        const float ka = Ks[m][ty];
        const float4 v4 = *(const float4*)&Vs[m][tx * 4];
        const float vv[4] = {v4.x, v4.y, v4.z, v4.w};

        if (ty == 0) {
            #pragma unroll
            for (int j = 0; j < 4; j++) acc0[j] += vv[j];
        }
        #pragma unroll
        for (int j = 0; j < 4; j++) acc1[j] = fmaf(ka, vv[j], acc1[j]);

        #pragma unroll
        for (int b = 0; b < 16; b++) {
            if (b >= tyw) {    // warp-uniform guard: skip ~half the pairs
                const float tc = ka * kb[b];
                #pragma unroll
                for (int j = 0; j < 4; j++)
                    acc2[b][j] = fmaf(tc, vv[j], acc2[b][j]);
            }
        }
    }

    float* Pb = g_P + ((size_t)(bh * NCH + t)) * NSE;
    if (ty == 0)
        *(float4*)&Pb[0 * HD + tx * 4] =
            make_float4(acc0[0], acc0[1], acc0[2], acc0[3]);
    *(float4*)&Pb[(1 + ty) * HD + tx * 4] =
        make_float4(0.25f * acc1[0], 0.25f * acc1[1],
                    0.25f * acc1[2], 0.25f * acc1[3]);

    const int fb0 = 17 + 15 * ty - (ty * (ty - 1)) / 2;  // f = fb0 + b for b>=ty
    #pragma unroll
    for (int b = 0; b < 16; b++) {
        if (b >= ty) {
            const float sc = (b == ty) ? 0.03125f : 0.0625f;
            *(float4*)&Pb[(fb0 + b) * HD + tx * 4] =
                make_float4(sc * acc2[b][0], sc * acc2[b][1],
                            sc * acc2[b][2], sc * acc2[b][3]);
        }
    }
}

// ---------------------------------------------------------------------------
// Build per-chunk denominator sums Pd[bh][t][f]
// ---------------------------------------------------------------------------
__global__ __launch_bounds__(256)
void build_den() {
    __shared__ __align__(16) float Ks[64][20];  // col 16 == 1.0 (const feature)
    const int tid = threadIdx.x;
    const int t = blockIdx.x, bh = blockIdx.y;
    const float* kbase = g_k + ((size_t)bh * L_ + t * 64) * FEAT;
    {
        const int row = tid >> 2, c = (tid & 3) * 4;
        *(float4*)&Ks[row][c] = *(const float4*)(kbase + row * FEAT + c);
    }
    if (tid < 64) Ks[tid][16] = 1.0f;
    __syncthreads();

    if (tid < NF) {
        const int f = tid;
        int ia, ib; float sc;
        if (f == 0)       { ia = 16; ib = 16; sc = 1.0f; }
        else if (f < 17)  { ia = f - 1; ib = 16; sc = 0.25f; }
        else {
            int fp = f - 17, a = 0, off = 0;
            while (off + (16 - a) <= fp) { off += 16 - a; a++; }
            ia = a; ib = a + fp - off;
            sc = (ia == ib) ? 0.03125f : 0.0625f;
        }
        float dp = 0.0f;
        for (int m = 0; m < 64; m++) dp += Ks[m][ia] * Ks[m][ib];
        g_Pd[((size_t)(bh * NCH + t)) * NF + f] = sc * dp;
    }
}

// ---------------------------------------------------------------------------
// Combined cumsum: C[t] = (exclusive prefix over t) + (total over all t)
// for both state and denominator.
// ---------------------------------------------------------------------------
__global__ __launch_bounds__(256)
void cumsum_kernel() {
    const int bh = blockIdx.x;
    const int idx = blockIdx.y * 256 + threadIdx.x;
    if (idx < NSE) {
        const float* p = g_P + (size_t)bh * NCH * NSE + idx;
        float*       c = g_C + (size_t)bh * NCH * NSE + idx;
        float pv[NCH]; float tot = 0.0f;
        #pragma unroll
        for (int t = 0; t < NCH; t++) { pv[t] = p[(size_t)t * NSE]; tot += pv[t]; }
        float run = tot;
        #pragma unroll
        for (int t = 0; t < NCH; t++) { c[(size_t)t * NSE] = run; run += pv[t]; }
    } else if (idx < NSE + NF) {
        const int j = idx - NSE;
        const float* p = g_Pd + (size_t)bh * NCH * NF + j;
        float*       c = g_Cd + (size_t)bh * NCH * NF + j;
        float pv[NCH]; float tot = 0.0f;
        #pragma unroll
        for (int t = 0; t < NCH; t++) { pv[t] = p[t * NF]; tot += pv[t]; }
        float run = tot;
        #pragma unroll
        for (int t = 0; t < NCH; t++) { c[t * NF] = run; run += pv[t]; }
    }
}

// ---------------------------------------------------------------------------
// Attention: diagonal causal tile (quadratic) + 153-feature linear eval
// against the combined state C[bh][qt].
// ---------------------------------------------------------------------------
__global__ __launch_bounds__(256)
void attn_kernel() {
    __shared__ __align__(16) float Qts[17][68];      // row 16 == 1.0
    __shared__ float cden_s[NF];
    __shared__ unsigned char tA[NF], tB[NF];
    __shared__ float rowsum_s[64];
    __shared__ __align__(16) float Ubuf[10404];      // union: diag tiles / PhiT

    float (*Kts)[68] = (float (*)[68])&Ubuf[0];             // 16x68
    float (*Vs)[64]  = (float (*)[64])&Ubuf[1088];          // 64x64
    float (*As)[68]  = (float (*)[68])&Ubuf[1088 + 4096];   // 64x68
    float (*PhiT)[68] = (float (*)[68])&Ubuf[0];            // 153x68 (reuse)

    const int tid = threadIdx.x;
    const int ty = tid >> 4;
    const int tx = tid & 15;
    const int qt = blockIdx.x;
    const int bh = blockIdx.y;
    const int lrow = tid >> 2;
    const int lfq  = (tid & 3) * 4;

    const float* qbase = g_q + (size_t)bh * L_ * FEAT;
    const float* kbase = g_k + (size_t)bh * L_ * FEAT;
    const float* vbase = g_v + (size_t)bh * L_ * HD;

    {
        const float4 qv = *(const float4*)(qbase + (qt * 64 + lrow) * FEAT + lfq);
        Qts[lfq + 0][lrow] = qv.x; Qts[lfq + 1][lrow] = qv.y;
        Qts[lfq + 2][lrow] = qv.z; Qts[lfq + 3][lrow] = qv.w;
        const float4 kv = *(const float4*)(kbase + (qt * 64 + lrow) * FEAT + lfq);
        Kts[lfq + 0][lrow] = kv.x; Kts[lfq + 1][lrow] = kv.y;
        Kts[lfq + 2][lrow] = kv.z; Kts[lfq + 3][lrow] = kv.w;
    }
    if (tid < 64) Qts[16][tid] = 1.0f;
    #pragma unroll
    for (int r = 0; r < 4; r++) {
        const int idx = tid + r * 256;
        const int row = idx >> 4, c = (idx & 15) * 4;
        *(float4*)&Vs[row][c] = *(const float4*)(vbase + (qt * 64 + row) * HD + c);
    }
    if (tid < NF) {
        const int f = tid;
        int ia, ib;
        if (f == 0)      { ia = 16; ib = 16; }
        else if (f < 17) { ia = f - 1; ib = 16; }
        else {
            int fp = f - 17, a = 0, off = 0;
            while (off + (16 - a) <= fp) { off += 16 - a; a++; }
            ia = a; ib = a + fp - off;
        }
        tA[f] = (unsigned char)ia;
        tB[f] = (unsigned char)ib;
        // 1/16: all 16 tx lanes add this redundantly, shfl-sum restores x16
        cden_s[f] = g_Cd[((size_t)(bh * NCH + qt)) * NF + f] * 0.0625f;
    }
    __syncthreads();

    float acc[4][4];
    float rsum[4] = {0, 0, 0, 0};
    #pragma unroll
    for (int i = 0; i < 4; i++)
        #pragma unroll
        for (int j = 0; j < 4; j++) acc[i][j] = 0.0f;

    // --- diagonal tile: S = Q K^T ---
    float s[4][4];
    #pragma unroll
    for (int i = 0; i < 4; i++)
        #pragma unroll
        for (int j = 0; j < 4; j++) s[i][j] = 0.0f;
    #pragma unroll
    for (int k = 0; k < 16; k++) {
        const float4 q4 = *(const float4*)&Qts[k][ty * 4];
        const float4 k4 = *(const float4*)&Kts[k][tx * 4];
        const float qa[4] = {q4.x, q4.y, q4.z, q4.w};
        const float ka[4] = {k4.x, k4.y, k4.z, k4.w};
        #pragma unroll
        for (int i = 0; i < 4; i++)
            #pragma unroll
            for (int j = 0; j < 4; j++)
                s[i][j] = fmaf(qa[i], ka[j], s[i][j]);
    }

    // A = f(s) masked strictly to m <= n within the tile
    #pragma unroll
    for (int i = 0; i < 4; i++) {
        float aw[4];
        #pragma unroll
        for (int j = 0; j < 4; j++) {
            const float sv = s[i][j];
            float a = fmaf(sv, fmaf(sv, 0.03125f, 0.25f), 1.0f);
            a = (tx * 4 + j <= ty * 4 + i) ? a : 0.0f;
            aw[j] = a;
            rsum[i] += a;
        }
        *(float4*)&As[ty * 4 + i][tx * 4] =
            make_float4(aw[0], aw[1], aw[2], aw[3]);
    }
    __syncthreads();

    // acc += A * V
    #pragma unroll 4
    for (int m = 0; m < 64; m += 4) {
        const float4 v0 = *(const float4*)&Vs[m + 0][tx * 4];
        const float4 v1 = *(const float4*)&Vs[m + 1][tx * 4];
        const float4 v2 = *(const float4*)&Vs[m + 2][tx * 4];
        const float4 v3 = *(const float4*)&Vs[m + 3][tx * 4];
        const float vv[4][4] = {
            {v0.x, v0.y, v0.z, v0.w},
            {v1.x, v1.y, v1.z, v1.w},
            {v2.x, v2.y, v2.z, v2.w},
            {v3.x, v3.y, v3.z, v3.w},
        };
        #pragma unroll
        for (int i = 0; i < 4; i++) {
            const float4 a4 = *(const float4*)&As[ty * 4 + i][m];
            const float ag[4] = {a4.x, a4.y, a4.z, a4.w};
            #pragma unroll
            for (int g = 0; g < 4; g++)
                #pragma unroll
                for (int j = 0; j < 4; j++)
                    acc[i][j] = fmaf(ag[g], vv[g][j], acc[i][j]);
        }
    }
    __syncthreads();   // done with Kts/Vs/As, Ubuf free

    // --- build PhiT[153][64]: phi_f(q)[row] = q[tA[f]] * q[tB[f]] ---
    for (int it = 0; it < 39; it++) {
        const int idx = tid + it * 256;
        if (idx < NF * 64) {
            const int f = idx >> 6, r = idx & 63;
            PhiT[f][r] = Qts[tA[f]][r] * Qts[tB[f]][r];
        }
    }
    __syncthreads();

    // --- eval: acc += PhiT^T * C (GEMM over 153 features), den likewise ---
    const float* Crow = g_C + ((size_t)(bh * NCH + qt)) * NSE + tx * 4;
    #pragma unroll 4
    for (int f = 0; f < NF; f++) {
        const float4 a4 = *(const float4*)&PhiT[f][ty * 4];
        const float4 b4 = *(const float4*)(Crow + f * HD);
        const float cd = cden_s[f];
        const float aa[4] = {a4.x, a4.y, a4.z, a4.w};
        const float bb[4] = {b4.x, b4.y, b4.z, b4.w};
        #pragma unroll
        for (int i = 0; i < 4; i++) {
            rsum[i] = fmaf(aa[i], cd, rsum[i]);
            #pragma unroll
            for (int j = 0; j < 4; j++)
                acc[i][j] = fmaf(aa[i], bb[j], acc[i][j]);
        }
    }

    // reduce row sums across 16 tx lanes
    #pragma unroll
    for (int i = 0; i < 4; i++) {
        float r = rsum[i];
        r += __shfl_xor_sync(0xffffffffu, r, 1);
        r += __shfl_xor_sync(0xffffffffu, r, 2);
        r += __shfl_xor_sync(0xffffffffu, r, 4);
        r += __shfl_xor_sync(0xffffffffu, r, 8);
        if (tx == 0) rowsum_s[ty * 4 + i] = r;
    }
    __syncthreads();

    const int bb_ = bh / H_;
    const int h   = bh % H_;
    #pragma unroll
    for (int i = 0; i < 4; i++) {
        const float z = 1.0f / rowsum_s[ty * 4 + i];
        const int n_g = qt * 64 + ty * 4 + i;
        const float4 o = make_float4(acc[i][0] * z, acc[i][1] * z,
                                     acc[i][2] * z, acc[i][3] * z);
        *(float4*)&g_y[((size_t)(bb_ * L_ + n_g)) * DM + h * HD + tx * 4] = o;
    }
}

// ---------------------------------------------------------------------------
extern "C" void kernel_launch(void* const* d_in, const int* in_sizes, int n_in,
                              void* d_out, int out_size) {
    (void)in_sizes; (void)n_in; (void)out_size;
    const float* hs = (const float*)d_in[0];
    const float* Wq = (const float*)d_in[1];
    const float* Wk = (const float*)d_in[2];
    const float* Wv = (const float*)d_in[3];
    const float* Wo = (const float*)d_in[4];
    float* out = (float*)d_out;

    float *qp, *kp, *vp, *yp;
    cudaGetSymbolAddress((void**)&qp, g_q);
    cudaGetSymbolAddress((void**)&kp, g_k);
    cudaGetSymbolAddress((void**)&vp, g_v);
    cudaGetSymbolAddress((void**)&yp, g_y);

    // Projections
    sgemm_proj<192, H_, FEAT><<<dim3(3, MTOT / 64), 256>>>(hs, Wq, qp);
    sgemm_proj<192, H_, FEAT><<<dim3(3, MTOT / 64), 256>>>(hs, Wk, kp);
    sgemm_proj<768, H_, HD><<<dim3(12, MTOT / 64), 256>>>(hs, Wv, vp);

    // Linear-attention state pipeline
    build_state<<<dim3(NCH, BH), 256>>>();
    build_den<<<dim3(NCH, BH), 256>>>();
    cumsum_kernel<<<dim3(BH, (NSE + NF + 255) / 256), 256>>>();

    // Attention: diagonal quadratic + linear eval
    attn_kernel<<<dim3(L_ / 64, BH), 256>>>();

    // Output projection
    sgemm_proj<768, 1, DM><<<dim3(12, MTOT / 64), 256>>>(yp, Wo, out);
}